// round 10
// baseline (speedup 1.0000x reference)
#include <cuda_runtime.h>
#include <math.h>

#define Nn 1024
#define Cc 8192
#define ODim 128
#define EPSF 1e-15f
#define CLIPMAXF 10000.0f
#define NB 16
#define NS 8                       // s/inner/t blocks (FIRST: spin-wait, must be early)
#define NG 48                      // 3 Gram tiles x 16 K-chunks
#define NPAIR 272                  // 136 triangular 64x64 tiles x 2 j-halves
#define NTOT (NS + NG + NPAIR)     // 328

// ---------- device state (zero at load; restored each run) ----------
__device__ float    g_colR[Nn];          // atomics; re-zeroed by finalize
__device__ float    g_inner[Nn];         // overwritten
__device__ float    g_t[Nn];             // overwritten
__device__ float    g_sPart[16][ODim];   // overwritten
__device__ float    g_G[3][4096];        // atomics; re-zeroed by last G-block
__device__ double   g_normG;             // overwritten
__device__ double   g_sumsqR, g_overlap, g_exceed, g_shape, g_positive;
__device__ unsigned g_done, g_doneS, g_doneG;

__global__ void __launch_bounds__(256, 3)
k_all(const int* __restrict__ idI, const int* __restrict__ par,
      const float* __restrict__ omega, const float* __restrict__ child,
      const float* __restrict__ resv, const float* __restrict__ leaves,
      const float* __restrict__ layerDist, float* __restrict__ out)
{
    __shared__ __align__(16) char sm[33024];
    __shared__ float sColI[64], sColJ[32];
    __shared__ double sAcc[8][2];
    __shared__ bool isLast;
    int tid = threadIdx.x, w = tid >> 5, lane = tid & 31;
    int b = blockIdx.x;

    if (b < NS) {
        // ========== s / inner / t blocks (early: they spin on each other) ==========
        int sb = b;
        int base = sb * 128;
        int half = tid & 1;
        {   // inner_i for 128 rows (2 threads per row)
            int row = base + (tid >> 1);
            const float4* p = (const float4*)(omega + (size_t)row * ODim + half * 64);
            float s = 0.f;
#pragma unroll
            for (int q = 0; q < 16; q++) {
                float4 v = p[q];
                s += v.x * v.x + v.y * v.y + v.z * v.z + v.w * v.w;
            }
            float o = __shfl_xor_sync(0xffffffffu, s, 1);
            if (half == 0) g_inner[row] = s + o;
        }
        {   // s partial: column sums over 64 rows
            int d = tid & 127, rh = tid >> 7;
            float sp = 0.f;
            for (int r = 0; r < 64; r++)
                sp += __ldg(omega + (size_t)(base + rh * 64 + r) * ODim + d);
            g_sPart[sb * 2 + rh][d] = sp;
        }
        __threadfence();
        __syncthreads();
        if (tid == 0) {
            atomicAdd(&g_doneS, 1u);
            volatile unsigned* ds = &g_doneS;
            while (*ds < NS) { }
        }
        __syncthreads();
        __threadfence();
        float* sS = (float*)sm;
        if (tid < ODim) {
            float s2 = 0.f;
#pragma unroll
            for (int q = 0; q < 16; q++) s2 += __ldcg(&g_sPart[q][tid]);
            sS[tid] = s2;
        }
        __syncthreads();
        {   // t_j = o_j . s
            int j = base + (tid >> 1);
            const float4* oj = (const float4*)(omega + (size_t)j * ODim + half * 64);
            const float4* s4 = (const float4*)(sS + half * 64);
            float tv = 0.f;
#pragma unroll
            for (int q = 0; q < 16; q++) {
                float4 a = oj[q], s = s4[q];
                tv += a.x * s.x + a.y * s.y + a.z * s.z + a.w * s.w;
            }
            float ot = __shfl_xor_sync(0xffffffffu, tv, 1);
            if (half == 0) g_t[j] = tv + ot;
        }
    } else if (b < NS + NG) {
        // ========== Gram: G = O^T O ==========
        float (*sO)[ODim] = (float(*)[ODim])sm;
        int gb = b - NS;
        int g = gb >> 4, kc = gb & 15;
        int P0 = (g == 2) ? 64 : 0;
        int Q0 = (g == 0) ? 0 : 64;

        const float4* og4 = (const float4*)(omega + (size_t)kc * 64 * ODim);
        for (int e = tid; e < 64 * 32; e += 256) ((float4*)sO)[e] = og4[e];
        __syncthreads();

        int pl_ = ((tid >> 4) & 15) * 4, ql_ = (tid & 15) * 4;
        float c[4][4];
#pragma unroll
        for (int m = 0; m < 4; m++)
#pragma unroll
            for (int n = 0; n < 4; n++) c[m][n] = 0.f;
#pragma unroll 8
        for (int k = 0; k < 64; k++) {
            float4 a  = *(const float4*)&sO[k][P0 + pl_];
            float4 bb = *(const float4*)&sO[k][Q0 + ql_];
            c[0][0] += a.x * bb.x; c[0][1] += a.x * bb.y; c[0][2] += a.x * bb.z; c[0][3] += a.x * bb.w;
            c[1][0] += a.y * bb.x; c[1][1] += a.y * bb.y; c[1][2] += a.y * bb.z; c[1][3] += a.y * bb.w;
            c[2][0] += a.z * bb.x; c[2][1] += a.z * bb.y; c[2][2] += a.z * bb.z; c[2][3] += a.z * bb.w;
            c[3][0] += a.w * bb.x; c[3][1] += a.w * bb.y; c[3][2] += a.w * bb.z; c[3][3] += a.w * bb.w;
        }
#pragma unroll
        for (int m = 0; m < 4; m++)
#pragma unroll
            for (int n = 0; n < 4; n++)
                atomicAdd(&g_G[g][(pl_ + m) * 64 + ql_ + n], c[m][n]);

        __threadfence();
        __shared__ bool lastG;
        if (tid == 0) lastG = (atomicAdd(&g_doneG, 1u) == NG - 1);
        __syncthreads();
        if (lastG) {
            __threadfence();
            double acc = 0.0;
            for (int e = tid; e < 3 * 4096; e += 256) {
                int gg = e >> 12, idx = e & 4095;
                float v = __ldcg(&g_G[gg][idx]);
                g_G[gg][idx] = 0.f;
                double d2 = (double)v * (double)v;
                acc += (gg == 1) ? 2.0 * d2 : d2;
            }
#pragma unroll
            for (int o = 16; o > 0; o >>= 1) acc += __shfl_xor_sync(0xffffffffu, acc, o);
            double* sR = (double*)sm;
            __syncthreads();
            if (lane == 0) sR[w] = acc;
            __syncthreads();
            if (tid == 0) {
                double tot = 0.0;
#pragma unroll
                for (int q = 0; q < 8; q++) tot += sR[q];
                g_normG = tot;
            }
        }
    } else {
        // ========== symmetric realdist: tile (bi<=bj) 64 i x 32 j ==========
        float (*sI)[48] = (float(*)[48])sm;
        int* sIdxI = (int*)(sm + 64 * 48 * 4);
        int p = b - NS - NG;
        int t = p >> 1, h = p & 1, bi = 0;
        while (t >= NB - bi) { t -= NB - bi; bi++; }
        int bj = bi + t;
        int I0 = bi * 64, J0 = bj * 64 + h * 32;

        if (tid < 64) { sIdxI[tid] = __ldg(idI + I0 + tid); sColI[tid] = 0.f; }
        if (tid < 32) sColJ[tid] = 0.f;

        int jglob = J0 + lane;
        int idxj = __ldg(idI + jglob);
        __syncthreads();

        // gathers first (long latency, in flight across staging)
        float aij[8], aji[8];
        int ibase = I0 + w * 8;
#pragma unroll
        for (int k = 0; k < 8; k++) {
            int ix = sIdxI[w * 8 + k];
            aij[k] = __ldg(layerDist + (size_t)ix * Cc + idxj);
            aji[k] = __ldg(layerDist + (size_t)idxj * Cc + ix);
        }

        // vectorized cl/ch staging: 64 rows x 8 float4
        for (int e = tid; e < 512; e += 256) {
            int ii = e >> 3, q = e & 7;
            float4 v = __ldg((const float4*)child + (size_t)sIdxI[ii] * 8 + q);
            *(float4*)&sI[ii][q * 4] = v;    // [0:16)=cl, [16:32)=ch
        }
        __syncthreads();
        for (int e = tid; e < 1024; e += 256) {
            int ii = e >> 4, d = e & 15;
            sI[ii][32 + d] = 1.0f / fmaxf(sI[ii][16 + d] - sI[ii][d], EPSF);
        }
        __syncthreads();

        // dim-outer / row-inner pair math
        float cd[8] = {0.f,0.f,0.f,0.f,0.f,0.f,0.f,0.f};
        float ov[8] = {0.f,0.f,0.f,0.f,0.f,0.f,0.f,0.f};
        const float4* pl = (const float4*)(child + (size_t)idxj * 32);
        const float4* ph = (const float4*)(child + (size_t)idxj * 32 + 16);
#pragma unroll
        for (int u = 0; u < 4; u++) {
            float4 l = pl[u], hh = ph[u];
            float4 v2;
            v2.x = 1.0f / fmaxf(hh.x - l.x, EPSF);
            v2.y = 1.0f / fmaxf(hh.y - l.y, EPSF);
            v2.z = 1.0f / fmaxf(hh.z - l.z, EPSF);
            v2.w = 1.0f / fmaxf(hh.w - l.w, EPSF);
#pragma unroll
            for (int k = 0; k < 8; k++) {
                float4 a  = *(const float4*)&sI[w * 8 + k][u * 4];
                float4 bb = *(const float4*)&sI[w * 8 + k][16 + u * 4];
                float4 vi = *(const float4*)&sI[w * 8 + k][32 + u * 4];
                cd[k] += fabsf(a.x - l.x) + fabsf(a.y - l.y)
                       + fabsf(a.z - l.z) + fabsf(a.w - l.w);
                float nx = fmaxf(fminf(bb.x, hh.x) - fmaxf(a.x, l.x), 0.f);
                float ny = fmaxf(fminf(bb.y, hh.y) - fmaxf(a.y, l.y), 0.f);
                float nz = fmaxf(fminf(bb.z, hh.z) - fmaxf(a.z, l.z), 0.f);
                float nw = fmaxf(fminf(bb.w, hh.w) - fmaxf(a.w, l.w), 0.f);
                ov[k] += nx * (vi.x + v2.x) + ny * (vi.y + v2.y)
                       + nz * (vi.z + v2.z) + nw * (vi.w + v2.w);
            }
        }

        // epilogue: NO per-k shuffle chains — smem accumulation
        float colsumJ = 0.f, ssqf = 0.f, ovf = 0.f;
#pragma unroll
        for (int k = 0; k < 8; k++) {
            int ig = ibase + k;
            float r1 = aij[k] + cd[k];
            float r2 = aji[k] + cd[k];
            if (ig < jglob) {
                colsumJ += r1;
                ssqf += r1 * r1 + r2 * r2;
                ovf  += ov[k];
                atomicAdd(&sColI[w * 8 + k], r2);
            } else if (ig == jglob) {
                colsumJ += r1;
                ssqf += r1 * r1;
            }
        }
        atomicAdd(&sColJ[lane], colsumJ);

        // single block reduce of the scalar partials (double)
        double ssq = (double)ssqf, ovd = (double)ovf;
#pragma unroll
        for (int o = 16; o > 0; o >>= 1) {
            ssq += __shfl_xor_sync(0xffffffffu, ssq, o);
            ovd += __shfl_xor_sync(0xffffffffu, ovd, o);
        }
        if (lane == 0) { sAcc[w][0] = ssq; sAcc[w][1] = ovd; }
        __syncthreads();
        if (tid == 0) {
            double t0 = 0.0, t1 = 0.0;
#pragma unroll
            for (int q = 0; q < 8; q++) { t0 += sAcc[q][0]; t1 += sAcc[q][1]; }
            atomicAdd(&g_sumsqR, t0);
            atomicAdd(&g_overlap, t1);
        }
        if (tid < 64) {
            float v = sColI[tid];
            if (v != 0.f) atomicAdd(&g_colR[I0 + tid], v);
        } else if (tid < 96) {
            atomicAdd(&g_colR[J0 + (tid - 64)], sColJ[tid - 64]);
        }

        // ---- per-node prep: first 32 pair blocks (bi==0), warp 0, lane's j ----
        if (p < 32 && w == 0) {
            int pp = __ldg(par + jglob);
            float leaf = __ldg(leaves + idxj);
            const float HPI = (float)(3.14159265358979323846 * 0.5);
            const float CAP = (float)(3.14159265358979323846 * 0.49999);
            const float4* prl = (const float4*)(resv + (size_t)pp * 32);
            const float4* prh = (const float4*)(resv + (size_t)pp * 32 + 16);
            float exceed = 0.f, shape = 0.f, pos = 0.f;
#pragma unroll
            for (int u = 0; u < 4; u++) {
                float4 cl = pl[u], ch = ph[u];
                float4 rl = prl[u], rh = prh[u];
                float cc[4] = {cl.x, cl.y, cl.z, cl.w};
                float ee[4] = {ch.x, ch.y, ch.z, ch.w};
                float aa[4] = {rl.x, rl.y, rl.z, rl.w};
                float zz[4] = {rh.x, rh.y, rh.z, rh.w};
#pragma unroll
                for (int d = 0; d < 4; d++) {
                    float diff = ee[d] - cc[d];
                    exceed += fmaxf((aa[d] + 1.0f) - cc[d], 0.f)
                            + fmaxf(ee[d] - (zz[d] + 1.0f), 0.f);
                    float numer = fmaxf(diff / (zz[d] - aa[d]), EPSF);
                    float sdiv  = fminf(numer / leaf, CAP);
                    shape += fminf(fabsf(tanf((sdiv - 1.0f) * HPI)), CLIPMAXF);
                    pos += fmaxf(expf(-diff), EPSF);
                }
            }
            double e = exceed, sh = shape, po = pos;
#pragma unroll
            for (int o = 16; o > 0; o >>= 1) {
                e  += __shfl_xor_sync(0xffffffffu, e,  o);
                sh += __shfl_xor_sync(0xffffffffu, sh, o);
                po += __shfl_xor_sync(0xffffffffu, po, o);
            }
            if (lane == 0) {
                atomicAdd(&g_exceed, e);
                atomicAdd(&g_shape, sh);
                atomicAdd(&g_positive, po);
            }
        }
    }

    // ================= last-block finalize + state restore =================
    __threadfence();
    if (tid == 0) isLast = (atomicAdd(&g_done, 1u) == NTOT - 1);
    __syncthreads();
    if (!isLast) return;
    __threadfence();

    double S1 = 0, S2 = 0, T1 = 0, CR = 0, CRI = 0, CRT = 0, s2a = 0;
#pragma unroll
    for (int q = 0; q < 4; q++) {
        int j = tid + q * 256;
        double inn = (double)__ldcg(&g_inner[j]);
        double tj  = (double)__ldcg(&g_t[j]);
        double cr  = (double)__ldcg(&g_colR[j]);
        g_colR[j] = 0.f;
        S1 += inn; S2 += inn * inn; T1 += inn * tj;
        CR += cr; CRI += cr * inn; CRT += cr * tj; s2a += cr * cr;
    }
#pragma unroll
    for (int o = 16; o > 0; o >>= 1) {
        S1 += __shfl_xor_sync(0xffffffffu, S1, o);
        S2 += __shfl_xor_sync(0xffffffffu, S2, o);
        T1 += __shfl_xor_sync(0xffffffffu, T1, o);
        CR += __shfl_xor_sync(0xffffffffu, CR, o);
        CRI += __shfl_xor_sync(0xffffffffu, CRI, o);
        CRT += __shfl_xor_sync(0xffffffffu, CRT, o);
        s2a += __shfl_xor_sync(0xffffffffu, s2a, o);
    }
    double* sR = (double*)sm;
    __syncthreads();
    if (lane == 0) {
        sR[w * 7 + 0] = S1; sR[w * 7 + 1] = S2; sR[w * 7 + 2] = T1;
        sR[w * 7 + 3] = CR; sR[w * 7 + 4] = CRI; sR[w * 7 + 5] = CRT;
        sR[w * 7 + 6] = s2a;
    }
    __syncthreads();
    if (tid == 0) {
        double a0 = 0, a1 = 0, a2 = 0, a3 = 0, a4 = 0, a5 = 0, a6 = 0;
#pragma unroll
        for (int q = 0; q < 8; q++) {
            a0 += sR[q * 7 + 0]; a1 += sR[q * 7 + 1]; a2 += sR[q * 7 + 2];
            a3 += sR[q * 7 + 3]; a4 += sR[q * 7 + 4]; a5 += sR[q * 7 + 5];
            a6 += sR[q * 7 + 6];
        }
        double sumsqA = 2.0 * Nn * a1 + 2.0 * a0 * a0 - 8.0 * a2 + 4.0 * __ldcg(&g_normG);
        double s1 = a0 * a3 + (double)Nn * a4 - 2.0 * a5 + (double)EPSF * a3;
        double sumsqR = __ldcg(&g_sumsqR);
        double nR = fmax(sqrt(sumsqR), 1e-15);
        double nA = fmax(sqrt(fmax(sumsqA, 0.0)), 1e-15);
        double val = sumsqA / (nA * nA) - 2.0 * (s1 / nR) / nA + (double)Nn * (a6 / (nR * nR));
        double lossDist = sqrt(fmax(val, 0.0));
        out[0] = (float)(lossDist + __ldcg(&g_shape) + __ldcg(&g_exceed)
                         + __ldcg(&g_overlap) + __ldcg(&g_positive));
        g_sumsqR = 0.0; g_overlap = 0.0; g_exceed = 0.0; g_shape = 0.0; g_positive = 0.0;
        g_done = 0u; g_doneS = 0u; g_doneG = 0u;
    }
}

// ---------------- launch ----------------
extern "C" void kernel_launch(void* const* d_in, const int* in_sizes, int n_in,
                              void* d_out, int out_size) {
    const int*   idI    = (const int*)d_in[0];
    const int*   par    = (const int*)d_in[1];
    const float* omega  = (const float*)d_in[2];
    const float* child  = (const float*)d_in[3];
    const float* resv   = (const float*)d_in[4];
    const float* leaves = (const float*)d_in[5];
    const float* layerD = (const float*)d_in[6];
    (void)in_sizes; (void)n_in; (void)out_size;

    k_all<<<NTOT, 256>>>(idI, par, omega, child, resv, leaves, layerD, (float*)d_out);
}

// round 11
// speedup vs baseline: 1.5059x; 1.5059x over previous
#include <cuda_runtime.h>
#include <math.h>

#define Nn 1024
#define Cc 8192
#define ODim 128
#define EPSF 1e-15f
#define CLIPMAXF 10000.0f
#define NB 16
#define NS 8                       // s/inner/t/prep blocks (FIRST: spin-wait, must be early)
#define NG 48                      // 3 Gram tiles x 16 K-chunks
#define NPAIR 272                  // 136 triangular 64x64 tiles x 2 j-halves
#define NTOT (NS + NG + NPAIR)     // 328

// ---------- device state (zero at load; restored each run) ----------
__device__ float    g_colR[Nn];          // atomics; re-zeroed by finalize
__device__ float    g_inner[Nn];         // overwritten
__device__ float    g_t[Nn];             // overwritten
__device__ float    g_sPart[16][ODim];   // overwritten
__device__ float    g_G[3][4096];        // atomics; re-zeroed by last G-block
__device__ double   g_normG;             // overwritten
__device__ double   g_sumsqR, g_overlap, g_exceed, g_shape, g_positive;
__device__ unsigned g_done, g_doneS, g_doneG;

__global__ void __launch_bounds__(256, 3)
k_all(const int* __restrict__ idI, const int* __restrict__ par,
      const float* __restrict__ omega, const float* __restrict__ child,
      const float* __restrict__ resv, const float* __restrict__ leaves,
      const float* __restrict__ layerDist, float* __restrict__ out)
{
    __shared__ __align__(16) char sm[33024];
    __shared__ double sAcc[8][2];
    __shared__ bool isLast;
    int tid = threadIdx.x, w = tid >> 5, lane = tid & 31;
    int b = blockIdx.x;

    if (b < NS) {
        // ========== s / inner / t / prep blocks ==========
        int sb = b;
        int base = sb * 128;
        int half = tid & 1;
        {   // inner_i for 128 rows (2 threads per row)
            int row = base + (tid >> 1);
            const float4* p = (const float4*)(omega + (size_t)row * ODim + half * 64);
            float s = 0.f;
#pragma unroll
            for (int q = 0; q < 16; q++) {
                float4 v = p[q];
                s += v.x * v.x + v.y * v.y + v.z * v.z + v.w * v.w;
            }
            float o = __shfl_xor_sync(0xffffffffu, s, 1);
            if (half == 0) g_inner[row] = s + o;
        }
        {   // s partial: column sums over 64 rows
            int d = tid & 127, rh = tid >> 7;
            float sp = 0.f;
            for (int r = 0; r < 64; r++)
                sp += __ldg(omega + (size_t)(base + rh * 64 + r) * ODim + d);
            g_sPart[sb * 2 + rh][d] = sp;
        }
        __threadfence();
        __syncthreads();
        if (tid == 0) {
            atomicAdd(&g_doneS, 1u);
            volatile unsigned* ds = &g_doneS;
            while (*ds < NS) { }
        }
        __syncthreads();
        __threadfence();
        float* sS = (float*)sm;
        if (tid < ODim) {
            float s2 = 0.f;
#pragma unroll
            for (int q = 0; q < 16; q++) s2 += __ldcg(&g_sPart[q][tid]);
            sS[tid] = s2;
        }
        __syncthreads();
        {   // t_j = o_j . s
            int j = base + (tid >> 1);
            const float4* oj = (const float4*)(omega + (size_t)j * ODim + half * 64);
            const float4* s4 = (const float4*)(sS + half * 64);
            float tv = 0.f;
#pragma unroll
            for (int q = 0; q < 16; q++) {
                float4 a = oj[q], s = s4[q];
                tv += a.x * s.x + a.y * s.y + a.z * s.z + a.w * s.w;
            }
            float ot = __shfl_xor_sync(0xffffffffu, tv, 1);
            if (half == 0) g_t[j] = tv + ot;
        }
        // ---- per-node prep: 128 nodes per s-block (moved off the pair blocks) ----
        if (tid < 128) {
            int n = base + tid;
            int idxn = __ldg(idI + n);
            int pp = __ldg(par + n);
            float leaf = __ldg(leaves + idxn);
            const float HPI = (float)(3.14159265358979323846 * 0.5);
            const float CAP = (float)(3.14159265358979323846 * 0.49999);
            const float4* pcl = (const float4*)(child + (size_t)idxn * 32);
            const float4* pch = (const float4*)(child + (size_t)idxn * 32 + 16);
            const float4* prl = (const float4*)(resv + (size_t)pp * 32);
            const float4* prh = (const float4*)(resv + (size_t)pp * 32 + 16);
            float exceed = 0.f, shape = 0.f, pos = 0.f;
#pragma unroll
            for (int u = 0; u < 4; u++) {
                float4 cl = pcl[u], ch = pch[u];
                float4 rl = prl[u], rh = prh[u];
                float cc[4] = {cl.x, cl.y, cl.z, cl.w};
                float ee[4] = {ch.x, ch.y, ch.z, ch.w};
                float aa[4] = {rl.x, rl.y, rl.z, rl.w};
                float zz[4] = {rh.x, rh.y, rh.z, rh.w};
#pragma unroll
                for (int d = 0; d < 4; d++) {
                    float diff = ee[d] - cc[d];
                    exceed += fmaxf((aa[d] + 1.0f) - cc[d], 0.f)
                            + fmaxf(ee[d] - (zz[d] + 1.0f), 0.f);
                    float numer = fmaxf(diff / (zz[d] - aa[d]), EPSF);
                    float sdiv  = fminf(numer / leaf, CAP);
                    shape += fminf(fabsf(tanf((sdiv - 1.0f) * HPI)), CLIPMAXF);
                    pos += fmaxf(expf(-diff), EPSF);
                }
            }
            double e = exceed, sh = shape, po = pos;
#pragma unroll
            for (int o = 16; o > 0; o >>= 1) {
                e  += __shfl_xor_sync(0xffffffffu, e,  o);
                sh += __shfl_xor_sync(0xffffffffu, sh, o);
                po += __shfl_xor_sync(0xffffffffu, po, o);
            }
            if (lane == 0) {
                atomicAdd(&g_exceed, e);
                atomicAdd(&g_shape, sh);
                atomicAdd(&g_positive, po);
            }
        }
    } else if (b < NS + NG) {
        // ========== Gram: G = O^T O ==========
        float (*sO)[ODim] = (float(*)[ODim])sm;
        int gb = b - NS;
        int g = gb >> 4, kc = gb & 15;
        int P0 = (g == 2) ? 64 : 0;
        int Q0 = (g == 0) ? 0 : 64;

        const float4* og4 = (const float4*)(omega + (size_t)kc * 64 * ODim);
        for (int e = tid; e < 64 * 32; e += 256) ((float4*)sO)[e] = og4[e];
        __syncthreads();

        int pl_ = ((tid >> 4) & 15) * 4, ql_ = (tid & 15) * 4;
        float c[4][4];
#pragma unroll
        for (int m = 0; m < 4; m++)
#pragma unroll
            for (int n = 0; n < 4; n++) c[m][n] = 0.f;
#pragma unroll 8
        for (int k = 0; k < 64; k++) {
            float4 a  = *(const float4*)&sO[k][P0 + pl_];
            float4 bb = *(const float4*)&sO[k][Q0 + ql_];
            c[0][0] += a.x * bb.x; c[0][1] += a.x * bb.y; c[0][2] += a.x * bb.z; c[0][3] += a.x * bb.w;
            c[1][0] += a.y * bb.x; c[1][1] += a.y * bb.y; c[1][2] += a.y * bb.z; c[1][3] += a.y * bb.w;
            c[2][0] += a.z * bb.x; c[2][1] += a.z * bb.y; c[2][2] += a.z * bb.z; c[2][3] += a.z * bb.w;
            c[3][0] += a.w * bb.x; c[3][1] += a.w * bb.y; c[3][2] += a.w * bb.z; c[3][3] += a.w * bb.w;
        }
#pragma unroll
        for (int m = 0; m < 4; m++)
#pragma unroll
            for (int n = 0; n < 4; n++)
                atomicAdd(&g_G[g][(pl_ + m) * 64 + ql_ + n], c[m][n]);

        __threadfence();
        __shared__ bool lastG;
        if (tid == 0) lastG = (atomicAdd(&g_doneG, 1u) == NG - 1);
        __syncthreads();
        if (lastG) {
            __threadfence();
            double acc = 0.0;
            for (int e = tid; e < 3 * 4096; e += 256) {
                int gg = e >> 12, idx = e & 4095;
                float v = __ldcg(&g_G[gg][idx]);
                g_G[gg][idx] = 0.f;
                double d2 = (double)v * (double)v;
                acc += (gg == 1) ? 2.0 * d2 : d2;
            }
#pragma unroll
            for (int o = 16; o > 0; o >>= 1) acc += __shfl_xor_sync(0xffffffffu, acc, o);
            double* sR = (double*)sm;
            __syncthreads();
            if (lane == 0) sR[w] = acc;
            __syncthreads();
            if (tid == 0) {
                double tot = 0.0;
#pragma unroll
                for (int q = 0; q < 8; q++) tot += sR[q];
                g_normG = tot;
            }
        }
    } else {
        // ========== symmetric realdist: tile (bi<=bj) 64 i x 32 j ==========
        float (*sI)[48] = (float(*)[48])sm;
        int* sIdxI = (int*)(sm + 64 * 48 * 4);
        int p = b - NS - NG;
        int t = p >> 1, h = p & 1, bi = 0;
        while (t >= NB - bi) { t -= NB - bi; bi++; }
        int bj = bi + t;
        int I0 = bi * 64, J0 = bj * 64 + h * 32;

        if (tid < 64) sIdxI[tid] = __ldg(idI + I0 + tid);

        int jglob = J0 + lane;
        int idxj = __ldg(idI + jglob);
        __syncthreads();

        for (int e = tid; e < 64 * 16; e += 256) {
            int ii = e >> 4, d = e & 15;
            int ix = sIdxI[ii];
            float cl = __ldg(child + (size_t)ix * 32 + d);
            float ch = __ldg(child + (size_t)ix * 32 + 16 + d);
            sI[ii][d] = cl; sI[ii][16 + d] = ch;
            sI[ii][32 + d] = 1.0f / fmaxf(ch - cl, EPSF);
        }
        // gathers: both orders for this warp's 8 i-rows (MLP=16)
        float aij[8], aji[8];
        int ibase = I0 + w * 8;
#pragma unroll
        for (int k = 0; k < 8; k++) {
            int ix = sIdxI[w * 8 + k];
            aij[k] = __ldg(layerDist + (size_t)ix * Cc + idxj);
            aji[k] = __ldg(layerDist + (size_t)idxj * Cc + ix);
        }
        __syncthreads();

        // dim-outer / row-inner: one (l,h,v) j-triple live at a time
        float cd[8] = {0.f,0.f,0.f,0.f,0.f,0.f,0.f,0.f};
        float ov[8] = {0.f,0.f,0.f,0.f,0.f,0.f,0.f,0.f};
        const float4* pl = (const float4*)(child + (size_t)idxj * 32);
        const float4* ph = (const float4*)(child + (size_t)idxj * 32 + 16);
#pragma unroll
        for (int u = 0; u < 4; u++) {
            float4 l = pl[u], hh = ph[u];
            float4 v2;
            v2.x = 1.0f / fmaxf(hh.x - l.x, EPSF);
            v2.y = 1.0f / fmaxf(hh.y - l.y, EPSF);
            v2.z = 1.0f / fmaxf(hh.z - l.z, EPSF);
            v2.w = 1.0f / fmaxf(hh.w - l.w, EPSF);
#pragma unroll
            for (int k = 0; k < 8; k++) {
                float4 a  = *(const float4*)&sI[w * 8 + k][u * 4];
                float4 bb = *(const float4*)&sI[w * 8 + k][16 + u * 4];
                float4 vi = *(const float4*)&sI[w * 8 + k][32 + u * 4];
                cd[k] += fabsf(a.x - l.x) + fabsf(a.y - l.y)
                       + fabsf(a.z - l.z) + fabsf(a.w - l.w);
                float nx = fmaxf(fminf(bb.x, hh.x) - fmaxf(a.x, l.x), 0.f);
                float ny = fmaxf(fminf(bb.y, hh.y) - fmaxf(a.y, l.y), 0.f);
                float nz = fmaxf(fminf(bb.z, hh.z) - fmaxf(a.z, l.z), 0.f);
                float nw = fmaxf(fminf(bb.w, hh.w) - fmaxf(a.w, l.w), 0.f);
                ov[k] += nx * (vi.x + v2.x) + ny * (vi.y + v2.y)
                       + nz * (vi.z + v2.z) + nw * (vi.w + v2.w);
            }
        }

        float colsumJ = 0.f;
        double ssq = 0.0, ovd = 0.0;
#pragma unroll
        for (int k = 0; k < 8; k++) {
            int ig = ibase + k;
            float r1 = aij[k] + cd[k];
            float r2 = aji[k] + cd[k];
            float wv = 0.f;
            if (ig < jglob) {
                colsumJ += r1;
                ssq += (double)(r1 * r1 + r2 * r2);
                ovd += (double)ov[k];
                wv = r2;
            } else if (ig == jglob) {
                colsumJ += r1;
                ssq += (double)(r1 * r1);
            }
#pragma unroll
            for (int o = 16; o > 0; o >>= 1) wv += __shfl_xor_sync(0xffffffffu, wv, o);
            if (lane == 0 && wv != 0.f) atomicAdd(&g_colR[ig], wv);
        }
        atomicAdd(&g_colR[jglob], colsumJ);

        // block-level fp64 reduce: 1 atomic per scalar per block
#pragma unroll
        for (int o = 16; o > 0; o >>= 1) {
            ssq += __shfl_xor_sync(0xffffffffu, ssq, o);
            ovd += __shfl_xor_sync(0xffffffffu, ovd, o);
        }
        if (lane == 0) { sAcc[w][0] = ssq; sAcc[w][1] = ovd; }
        __syncthreads();
        if (tid == 0) {
            double t0 = 0.0, t1 = 0.0;
#pragma unroll
            for (int q = 0; q < 8; q++) { t0 += sAcc[q][0]; t1 += sAcc[q][1]; }
            atomicAdd(&g_sumsqR, t0);
            atomicAdd(&g_overlap, t1);
        }
    }

    // ================= last-block finalize + state restore =================
    __threadfence();
    if (tid == 0) isLast = (atomicAdd(&g_done, 1u) == NTOT - 1);
    __syncthreads();
    if (!isLast) return;
    __threadfence();

    double S1 = 0, S2 = 0, T1 = 0, CR = 0, CRI = 0, CRT = 0, s2a = 0;
#pragma unroll
    for (int q = 0; q < 4; q++) {
        int j = tid + q * 256;
        double inn = (double)__ldcg(&g_inner[j]);
        double tj  = (double)__ldcg(&g_t[j]);
        double cr  = (double)__ldcg(&g_colR[j]);
        g_colR[j] = 0.f;
        S1 += inn; S2 += inn * inn; T1 += inn * tj;
        CR += cr; CRI += cr * inn; CRT += cr * tj; s2a += cr * cr;
    }
#pragma unroll
    for (int o = 16; o > 0; o >>= 1) {
        S1 += __shfl_xor_sync(0xffffffffu, S1, o);
        S2 += __shfl_xor_sync(0xffffffffu, S2, o);
        T1 += __shfl_xor_sync(0xffffffffu, T1, o);
        CR += __shfl_xor_sync(0xffffffffu, CR, o);
        CRI += __shfl_xor_sync(0xffffffffu, CRI, o);
        CRT += __shfl_xor_sync(0xffffffffu, CRT, o);
        s2a += __shfl_xor_sync(0xffffffffu, s2a, o);
    }
    double* sR = (double*)sm;
    __syncthreads();
    if (lane == 0) {
        sR[w * 7 + 0] = S1; sR[w * 7 + 1] = S2; sR[w * 7 + 2] = T1;
        sR[w * 7 + 3] = CR; sR[w * 7 + 4] = CRI; sR[w * 7 + 5] = CRT;
        sR[w * 7 + 6] = s2a;
    }
    __syncthreads();
    if (tid == 0) {
        double a0 = 0, a1 = 0, a2 = 0, a3 = 0, a4 = 0, a5 = 0, a6 = 0;
#pragma unroll
        for (int q = 0; q < 8; q++) {
            a0 += sR[q * 7 + 0]; a1 += sR[q * 7 + 1]; a2 += sR[q * 7 + 2];
            a3 += sR[q * 7 + 3]; a4 += sR[q * 7 + 4]; a5 += sR[q * 7 + 5];
            a6 += sR[q * 7 + 6];
        }
        double sumsqA = 2.0 * Nn * a1 + 2.0 * a0 * a0 - 8.0 * a2 + 4.0 * __ldcg(&g_normG);
        double s1 = a0 * a3 + (double)Nn * a4 - 2.0 * a5 + (double)EPSF * a3;
        double sumsqR = __ldcg(&g_sumsqR);
        double nR = fmax(sqrt(sumsqR), 1e-15);
        double nA = fmax(sqrt(fmax(sumsqA, 0.0)), 1e-15);
        double val = sumsqA / (nA * nA) - 2.0 * (s1 / nR) / nA + (double)Nn * (a6 / (nR * nR));
        double lossDist = sqrt(fmax(val, 0.0));
        out[0] = (float)(lossDist + __ldcg(&g_shape) + __ldcg(&g_exceed)
                         + __ldcg(&g_overlap) + __ldcg(&g_positive));
        g_sumsqR = 0.0; g_overlap = 0.0; g_exceed = 0.0; g_shape = 0.0; g_positive = 0.0;
        g_done = 0u; g_doneS = 0u; g_doneG = 0u;
    }
}

// ---------------- launch ----------------
extern "C" void kernel_launch(void* const* d_in, const int* in_sizes, int n_in,
                              void* d_out, int out_size) {
    const int*   idI    = (const int*)d_in[0];
    const int*   par    = (const int*)d_in[1];
    const float* omega  = (const float*)d_in[2];
    const float* child  = (const float*)d_in[3];
    const float* resv   = (const float*)d_in[4];
    const float* leaves = (const float*)d_in[5];
    const float* layerD = (const float*)d_in[6];
    (void)in_sizes; (void)n_in; (void)out_size;

    k_all<<<NTOT, 256>>>(idI, par, omega, child, resv, leaves, layerD, (float*)d_out);
}

// round 12
// speedup vs baseline: 1.5312x; 1.0168x over previous
#include <cuda_runtime.h>
#include <math.h>

#define Nn 1024
#define Cc 8192
#define ODim 128
#define EPSF 1e-15f
#define CLIPMAXF 10000.0f
#define NB2 32                     // 1024/32 tiles per side
#define NS 8                       // s/inner/t/prep blocks (FIRST: spin-wait, must be early)
#define NG 48                      // 3 Gram tiles x 16 K-chunks
#define NPAIR (NB2*(NB2+1)/2)      // 528 triangular 32x32 tiles
#define NTOT (NS + NG + NPAIR)     // 584

// ---------- device state (zero at load; restored each run) ----------
__device__ float    g_colR[Nn];          // atomics; re-zeroed by finalize
__device__ float    g_inner[Nn];         // overwritten
__device__ float    g_t[Nn];             // overwritten
__device__ float    g_sPart[16][ODim];   // overwritten
__device__ float    g_G[3][4096];        // atomics; re-zeroed by last G-block
__device__ double   g_normG;             // overwritten
__device__ double   g_sumsqR, g_overlap, g_exceed, g_shape, g_positive;
__device__ unsigned g_done, g_doneS, g_doneG;

__global__ void __launch_bounds__(256, 4)
k_all(const int* __restrict__ idI, const int* __restrict__ par,
      const float* __restrict__ omega, const float* __restrict__ child,
      const float* __restrict__ resv, const float* __restrict__ leaves,
      const float* __restrict__ layerDist, float* __restrict__ out)
{
    __shared__ __align__(16) char sm[33024];
    __shared__ double sAcc[8][2];
    __shared__ bool isLast;
    int tid = threadIdx.x, w = tid >> 5, lane = tid & 31;
    int b = blockIdx.x;

    if (b < NS) {
        // ========== s / inner / t / prep blocks ==========
        int sb = b;
        int base = sb * 128;
        int half = tid & 1;
        {   // inner_i for 128 rows (2 threads per row)
            int row = base + (tid >> 1);
            const float4* p = (const float4*)(omega + (size_t)row * ODim + half * 64);
            float s = 0.f;
#pragma unroll
            for (int q = 0; q < 16; q++) {
                float4 v = p[q];
                s += v.x * v.x + v.y * v.y + v.z * v.z + v.w * v.w;
            }
            float o = __shfl_xor_sync(0xffffffffu, s, 1);
            if (half == 0) g_inner[row] = s + o;
        }
        {   // s partial: column sums over 64 rows
            int d = tid & 127, rh = tid >> 7;
            float sp = 0.f;
            for (int r = 0; r < 64; r++)
                sp += __ldg(omega + (size_t)(base + rh * 64 + r) * ODim + d);
            g_sPart[sb * 2 + rh][d] = sp;
        }
        __threadfence();
        __syncthreads();
        if (tid == 0) {
            atomicAdd(&g_doneS, 1u);
            volatile unsigned* ds = &g_doneS;
            while (*ds < NS) { }
        }
        __syncthreads();
        __threadfence();
        float* sS = (float*)sm;
        if (tid < ODim) {
            float s2 = 0.f;
#pragma unroll
            for (int q = 0; q < 16; q++) s2 += __ldcg(&g_sPart[q][tid]);
            sS[tid] = s2;
        }
        __syncthreads();
        {   // t_j = o_j . s
            int j = base + (tid >> 1);
            const float4* oj = (const float4*)(omega + (size_t)j * ODim + half * 64);
            const float4* s4 = (const float4*)(sS + half * 64);
            float tv = 0.f;
#pragma unroll
            for (int q = 0; q < 16; q++) {
                float4 a = oj[q], s = s4[q];
                tv += a.x * s.x + a.y * s.y + a.z * s.z + a.w * s.w;
            }
            float ot = __shfl_xor_sync(0xffffffffu, tv, 1);
            if (half == 0) g_t[j] = tv + ot;
        }
        // ---- per-node prep: 128 nodes per s-block ----
        if (tid < 128) {
            int n = base + tid;
            int idxn = __ldg(idI + n);
            int pp = __ldg(par + n);
            float leaf = __ldg(leaves + idxn);
            const float HPI = (float)(3.14159265358979323846 * 0.5);
            const float CAP = (float)(3.14159265358979323846 * 0.49999);
            const float4* pcl = (const float4*)(child + (size_t)idxn * 32);
            const float4* pch = (const float4*)(child + (size_t)idxn * 32 + 16);
            const float4* prl = (const float4*)(resv + (size_t)pp * 32);
            const float4* prh = (const float4*)(resv + (size_t)pp * 32 + 16);
            float exceed = 0.f, shape = 0.f, pos = 0.f;
#pragma unroll
            for (int u = 0; u < 4; u++) {
                float4 cl = pcl[u], ch = pch[u];
                float4 rl = prl[u], rh = prh[u];
                float cc[4] = {cl.x, cl.y, cl.z, cl.w};
                float ee[4] = {ch.x, ch.y, ch.z, ch.w};
                float aa[4] = {rl.x, rl.y, rl.z, rl.w};
                float zz[4] = {rh.x, rh.y, rh.z, rh.w};
#pragma unroll
                for (int d = 0; d < 4; d++) {
                    float diff = ee[d] - cc[d];
                    exceed += fmaxf((aa[d] + 1.0f) - cc[d], 0.f)
                            + fmaxf(ee[d] - (zz[d] + 1.0f), 0.f);
                    float numer = fmaxf(diff / (zz[d] - aa[d]), EPSF);
                    float sdiv  = fminf(numer / leaf, CAP);
                    shape += fminf(fabsf(tanf((sdiv - 1.0f) * HPI)), CLIPMAXF);
                    pos += fmaxf(expf(-diff), EPSF);
                }
            }
            double e = exceed, sh = shape, po = pos;
#pragma unroll
            for (int o = 16; o > 0; o >>= 1) {
                e  += __shfl_xor_sync(0xffffffffu, e,  o);
                sh += __shfl_xor_sync(0xffffffffu, sh, o);
                po += __shfl_xor_sync(0xffffffffu, po, o);
            }
            if (lane == 0) {
                atomicAdd(&g_exceed, e);
                atomicAdd(&g_shape, sh);
                atomicAdd(&g_positive, po);
            }
        }
    } else if (b < NS + NG) {
        // ========== Gram: G = O^T O ==========
        float (*sO)[ODim] = (float(*)[ODim])sm;
        int gb = b - NS;
        int g = gb >> 4, kc = gb & 15;
        int P0 = (g == 2) ? 64 : 0;
        int Q0 = (g == 0) ? 0 : 64;

        const float4* og4 = (const float4*)(omega + (size_t)kc * 64 * ODim);
        for (int e = tid; e < 64 * 32; e += 256) ((float4*)sO)[e] = og4[e];
        __syncthreads();

        int pl_ = ((tid >> 4) & 15) * 4, ql_ = (tid & 15) * 4;
        float c[4][4];
#pragma unroll
        for (int m = 0; m < 4; m++)
#pragma unroll
            for (int n = 0; n < 4; n++) c[m][n] = 0.f;
#pragma unroll 8
        for (int k = 0; k < 64; k++) {
            float4 a  = *(const float4*)&sO[k][P0 + pl_];
            float4 bb = *(const float4*)&sO[k][Q0 + ql_];
            c[0][0] += a.x * bb.x; c[0][1] += a.x * bb.y; c[0][2] += a.x * bb.z; c[0][3] += a.x * bb.w;
            c[1][0] += a.y * bb.x; c[1][1] += a.y * bb.y; c[1][2] += a.y * bb.z; c[1][3] += a.y * bb.w;
            c[2][0] += a.z * bb.x; c[2][1] += a.z * bb.y; c[2][2] += a.z * bb.z; c[2][3] += a.z * bb.w;
            c[3][0] += a.w * bb.x; c[3][1] += a.w * bb.y; c[3][2] += a.w * bb.z; c[3][3] += a.w * bb.w;
        }
#pragma unroll
        for (int m = 0; m < 4; m++)
#pragma unroll
            for (int n = 0; n < 4; n++)
                atomicAdd(&g_G[g][(pl_ + m) * 64 + ql_ + n], c[m][n]);

        __threadfence();
        __shared__ bool lastG;
        if (tid == 0) lastG = (atomicAdd(&g_doneG, 1u) == NG - 1);
        __syncthreads();
        if (lastG) {
            __threadfence();
            double acc = 0.0;
            for (int e = tid; e < 3 * 4096; e += 256) {
                int gg = e >> 12, idx = e & 4095;
                float v = __ldcg(&g_G[gg][idx]);
                g_G[gg][idx] = 0.f;
                double d2 = (double)v * (double)v;
                acc += (gg == 1) ? 2.0 * d2 : d2;
            }
#pragma unroll
            for (int o = 16; o > 0; o >>= 1) acc += __shfl_xor_sync(0xffffffffu, acc, o);
            double* sR = (double*)sm;
            __syncthreads();
            if (lane == 0) sR[w] = acc;
            __syncthreads();
            if (tid == 0) {
                double tot = 0.0;
#pragma unroll
                for (int q = 0; q < 8; q++) tot += sR[q];
                g_normG = tot;
            }
        }
    } else {
        // ========== symmetric realdist: triangular tile (bi<=bj) 32 i x 32 j ==========
        float (*sI)[48] = (float(*)[48])sm;
        int* sIdxI = (int*)(sm + 32 * 48 * 4);
        int p = b - NS - NG;
        int t = p, bi = 0;
        while (t >= NB2 - bi) { t -= NB2 - bi; bi++; }
        int bj = bi + t;
        int I0 = bi * 32, J0 = bj * 32;

        if (tid < 32) sIdxI[tid] = __ldg(idI + I0 + tid);

        int jglob = J0 + lane;
        int idxj = __ldg(idI + jglob);
        __syncthreads();

        for (int e = tid; e < 32 * 16; e += 256) {
            int ii = e >> 4, d = e & 15;
            int ix = sIdxI[ii];
            float cl = __ldg(child + (size_t)ix * 32 + d);
            float ch = __ldg(child + (size_t)ix * 32 + 16 + d);
            sI[ii][d] = cl; sI[ii][16 + d] = ch;
            sI[ii][32 + d] = 1.0f / fmaxf(ch - cl, EPSF);
        }
        // gathers: both orders for this warp's 4 i-rows (MLP=8)
        float aij[4], aji[4];
        int ibase = I0 + w * 4;
#pragma unroll
        for (int k = 0; k < 4; k++) {
            int ix = sIdxI[w * 4 + k];
            aij[k] = __ldg(layerDist + (size_t)ix * Cc + idxj);
            aji[k] = __ldg(layerDist + (size_t)idxj * Cc + ix);
        }
        __syncthreads();

        // dim-outer / row-inner: one (l,h,v) j-triple live at a time
        float cd[4] = {0.f,0.f,0.f,0.f};
        float ov[4] = {0.f,0.f,0.f,0.f};
        const float4* pl = (const float4*)(child + (size_t)idxj * 32);
        const float4* ph = (const float4*)(child + (size_t)idxj * 32 + 16);
#pragma unroll
        for (int u = 0; u < 4; u++) {
            float4 l = pl[u], hh = ph[u];
            float4 v2;
            v2.x = 1.0f / fmaxf(hh.x - l.x, EPSF);
            v2.y = 1.0f / fmaxf(hh.y - l.y, EPSF);
            v2.z = 1.0f / fmaxf(hh.z - l.z, EPSF);
            v2.w = 1.0f / fmaxf(hh.w - l.w, EPSF);
#pragma unroll
            for (int k = 0; k < 4; k++) {
                float4 a  = *(const float4*)&sI[w * 4 + k][u * 4];
                float4 bb = *(const float4*)&sI[w * 4 + k][16 + u * 4];
                float4 vi = *(const float4*)&sI[w * 4 + k][32 + u * 4];
                cd[k] += fabsf(a.x - l.x) + fabsf(a.y - l.y)
                       + fabsf(a.z - l.z) + fabsf(a.w - l.w);
                float nx = fmaxf(fminf(bb.x, hh.x) - fmaxf(a.x, l.x), 0.f);
                float ny = fmaxf(fminf(bb.y, hh.y) - fmaxf(a.y, l.y), 0.f);
                float nz = fmaxf(fminf(bb.z, hh.z) - fmaxf(a.z, l.z), 0.f);
                float nw = fmaxf(fminf(bb.w, hh.w) - fmaxf(a.w, l.w), 0.f);
                ov[k] += nx * (vi.x + v2.x) + ny * (vi.y + v2.y)
                       + nz * (vi.z + v2.z) + nw * (vi.w + v2.w);
            }
        }

        float colsumJ = 0.f;
        double ssq = 0.0, ovd = 0.0;
#pragma unroll
        for (int k = 0; k < 4; k++) {
            int ig = ibase + k;
            float r1 = aij[k] + cd[k];
            float r2 = aji[k] + cd[k];
            float wv = 0.f;
            if (ig < jglob) {
                colsumJ += r1;
                ssq += (double)(r1 * r1 + r2 * r2);
                ovd += (double)ov[k];
                wv = r2;
            } else if (ig == jglob) {
                colsumJ += r1;
                ssq += (double)(r1 * r1);
            }
#pragma unroll
            for (int o = 16; o > 0; o >>= 1) wv += __shfl_xor_sync(0xffffffffu, wv, o);
            if (lane == 0 && wv != 0.f) atomicAdd(&g_colR[ig], wv);
        }
        atomicAdd(&g_colR[jglob], colsumJ);

        // block-level fp64 reduce: 1 atomic per scalar per block
#pragma unroll
        for (int o = 16; o > 0; o >>= 1) {
            ssq += __shfl_xor_sync(0xffffffffu, ssq, o);
            ovd += __shfl_xor_sync(0xffffffffu, ovd, o);
        }
        if (lane == 0) { sAcc[w][0] = ssq; sAcc[w][1] = ovd; }
        __syncthreads();
        if (tid == 0) {
            double t0 = 0.0, t1 = 0.0;
#pragma unroll
            for (int q = 0; q < 8; q++) { t0 += sAcc[q][0]; t1 += sAcc[q][1]; }
            atomicAdd(&g_sumsqR, t0);
            atomicAdd(&g_overlap, t1);
        }
    }

    // ================= last-block finalize + state restore =================
    __threadfence();
    if (tid == 0) isLast = (atomicAdd(&g_done, 1u) == NTOT - 1);
    __syncthreads();
    if (!isLast) return;
    __threadfence();

    double S1 = 0, S2 = 0, T1 = 0, CR = 0, CRI = 0, CRT = 0, s2a = 0;
#pragma unroll
    for (int q = 0; q < 4; q++) {
        int j = tid + q * 256;
        double inn = (double)__ldcg(&g_inner[j]);
        double tj  = (double)__ldcg(&g_t[j]);
        double cr  = (double)__ldcg(&g_colR[j]);
        g_colR[j] = 0.f;
        S1 += inn; S2 += inn * inn; T1 += inn * tj;
        CR += cr; CRI += cr * inn; CRT += cr * tj; s2a += cr * cr;
    }
#pragma unroll
    for (int o = 16; o > 0; o >>= 1) {
        S1 += __shfl_xor_sync(0xffffffffu, S1, o);
        S2 += __shfl_xor_sync(0xffffffffu, S2, o);
        T1 += __shfl_xor_sync(0xffffffffu, T1, o);
        CR += __shfl_xor_sync(0xffffffffu, CR, o);
        CRI += __shfl_xor_sync(0xffffffffu, CRI, o);
        CRT += __shfl_xor_sync(0xffffffffu, CRT, o);
        s2a += __shfl_xor_sync(0xffffffffu, s2a, o);
    }
    double* sR = (double*)sm;
    __syncthreads();
    if (lane == 0) {
        sR[w * 7 + 0] = S1; sR[w * 7 + 1] = S2; sR[w * 7 + 2] = T1;
        sR[w * 7 + 3] = CR; sR[w * 7 + 4] = CRI; sR[w * 7 + 5] = CRT;
        sR[w * 7 + 6] = s2a;
    }
    __syncthreads();
    if (tid == 0) {
        double a0 = 0, a1 = 0, a2 = 0, a3 = 0, a4 = 0, a5 = 0, a6 = 0;
#pragma unroll
        for (int q = 0; q < 8; q++) {
            a0 += sR[q * 7 + 0]; a1 += sR[q * 7 + 1]; a2 += sR[q * 7 + 2];
            a3 += sR[q * 7 + 3]; a4 += sR[q * 7 + 4]; a5 += sR[q * 7 + 5];
            a6 += sR[q * 7 + 6];
        }
        double sumsqA = 2.0 * Nn * a1 + 2.0 * a0 * a0 - 8.0 * a2 + 4.0 * __ldcg(&g_normG);
        double s1 = a0 * a3 + (double)Nn * a4 - 2.0 * a5 + (double)EPSF * a3;
        double sumsqR = __ldcg(&g_sumsqR);
        double nR = fmax(sqrt(sumsqR), 1e-15);
        double nA = fmax(sqrt(fmax(sumsqA, 0.0)), 1e-15);
        double val = sumsqA / (nA * nA) - 2.0 * (s1 / nR) / nA + (double)Nn * (a6 / (nR * nR));
        double lossDist = sqrt(fmax(val, 0.0));
        out[0] = (float)(lossDist + __ldcg(&g_shape) + __ldcg(&g_exceed)
                         + __ldcg(&g_overlap) + __ldcg(&g_positive));
        g_sumsqR = 0.0; g_overlap = 0.0; g_exceed = 0.0; g_shape = 0.0; g_positive = 0.0;
        g_done = 0u; g_doneS = 0u; g_doneG = 0u;
    }
}

// ---------------- launch ----------------
extern "C" void kernel_launch(void* const* d_in, const int* in_sizes, int n_in,
                              void* d_out, int out_size) {
    const int*   idI    = (const int*)d_in[0];
    const int*   par    = (const int*)d_in[1];
    const float* omega  = (const float*)d_in[2];
    const float* child  = (const float*)d_in[3];
    const float* resv   = (const float*)d_in[4];
    const float* leaves = (const float*)d_in[5];
    const float* layerD = (const float*)d_in[6];
    (void)in_sizes; (void)n_in; (void)out_size;

    k_all<<<NTOT, 256>>>(idI, par, omega, child, resv, leaves, layerD, (float*)d_out);
}

// round 13
// speedup vs baseline: 1.5423x; 1.0072x over previous
#include <cuda_runtime.h>
#include <math.h>

#define Nn 1024
#define Cc 8192
#define ODim 128
#define EPSF 1e-15f
#define CLIPMAXF 10000.0f
#define NB2 32                     // 1024/32 tiles per side
#define NS 8                       // s/inner/t/prep blocks (FIRST: spin-wait, must be early)
#define NG 48                      // 3 Gram tiles x 16 K-chunks
#define NPAIR (NB2*(NB2+1)/2)      // 528 triangular 32x32 tiles
#define NTOT (NS + NG + NPAIR)     // 584

// ---------- device state (zero at load; restored each run) ----------
__device__ float    g_colR[Nn];          // atomics; re-zeroed by finalize
__device__ float    g_inner[Nn];         // overwritten
__device__ float    g_t[Nn];             // overwritten
__device__ float    g_sPart[16][ODim];   // overwritten
__device__ float    g_G[3][4096];        // atomics; re-zeroed by last G-block
__device__ double   g_normG;             // overwritten
__device__ double   g_sumsqR, g_overlap, g_exceed, g_shape, g_positive;
__device__ unsigned g_done, g_doneS, g_doneG;

__global__ void __launch_bounds__(256, 4)
k_all(const int* __restrict__ idI, const int* __restrict__ par,
      const float* __restrict__ omega, const float* __restrict__ child,
      const float* __restrict__ resv, const float* __restrict__ leaves,
      const float* __restrict__ layerDist, float* __restrict__ out)
{
    __shared__ __align__(16) char sm[33024];
    __shared__ double sAcc[8][2];
    __shared__ bool isLast;
    int tid = threadIdx.x, w = tid >> 5, lane = tid & 31;
    int b = blockIdx.x;

    if (b < NS) {
        // ========== s / inner / t / prep blocks ==========
        int sb = b;
        int base = sb * 128;
        int half = tid & 1;
        {   // inner_i for 128 rows (2 threads per row)
            int row = base + (tid >> 1);
            const float4* p = (const float4*)(omega + (size_t)row * ODim + half * 64);
            float s = 0.f;
#pragma unroll
            for (int q = 0; q < 16; q++) {
                float4 v = p[q];
                s += v.x * v.x + v.y * v.y + v.z * v.z + v.w * v.w;
            }
            float o = __shfl_xor_sync(0xffffffffu, s, 1);
            if (half == 0) g_inner[row] = s + o;
        }
        {   // s partial: column sums over 64 rows
            int d = tid & 127, rh = tid >> 7;
            float sp = 0.f;
            for (int r = 0; r < 64; r++)
                sp += __ldg(omega + (size_t)(base + rh * 64 + r) * ODim + d);
            g_sPart[sb * 2 + rh][d] = sp;
        }
        __threadfence();
        __syncthreads();
        if (tid == 0) {
            atomicAdd(&g_doneS, 1u);
            volatile unsigned* ds = &g_doneS;
            while (*ds < NS) { }
        }
        __syncthreads();
        __threadfence();
        float* sS = (float*)sm;
        if (tid < ODim) {
            float s2 = 0.f;
#pragma unroll
            for (int q = 0; q < 16; q++) s2 += __ldcg(&g_sPart[q][tid]);
            sS[tid] = s2;
        }
        __syncthreads();
        {   // t_j = o_j . s
            int j = base + (tid >> 1);
            const float4* oj = (const float4*)(omega + (size_t)j * ODim + half * 64);
            const float4* s4 = (const float4*)(sS + half * 64);
            float tv = 0.f;
#pragma unroll
            for (int q = 0; q < 16; q++) {
                float4 a = oj[q], s = s4[q];
                tv += a.x * s.x + a.y * s.y + a.z * s.z + a.w * s.w;
            }
            float ot = __shfl_xor_sync(0xffffffffu, tv, 1);
            if (half == 0) g_t[j] = tv + ot;
        }
        // ---- per-node prep: 128 nodes per s-block ----
        if (tid < 128) {
            int n = base + tid;
            int idxn = __ldg(idI + n);
            int pp = __ldg(par + n);
            float leaf = __ldg(leaves + idxn);
            const float HPI = (float)(3.14159265358979323846 * 0.5);
            const float CAP = (float)(3.14159265358979323846 * 0.49999);
            const float4* pcl = (const float4*)(child + (size_t)idxn * 32);
            const float4* pch = (const float4*)(child + (size_t)idxn * 32 + 16);
            const float4* prl = (const float4*)(resv + (size_t)pp * 32);
            const float4* prh = (const float4*)(resv + (size_t)pp * 32 + 16);
            float exceed = 0.f, shape = 0.f, pos = 0.f;
#pragma unroll
            for (int u = 0; u < 4; u++) {
                float4 cl = pcl[u], ch = pch[u];
                float4 rl = prl[u], rh = prh[u];
                float cc[4] = {cl.x, cl.y, cl.z, cl.w};
                float ee[4] = {ch.x, ch.y, ch.z, ch.w};
                float aa[4] = {rl.x, rl.y, rl.z, rl.w};
                float zz[4] = {rh.x, rh.y, rh.z, rh.w};
#pragma unroll
                for (int d = 0; d < 4; d++) {
                    float diff = ee[d] - cc[d];
                    exceed += fmaxf((aa[d] + 1.0f) - cc[d], 0.f)
                            + fmaxf(ee[d] - (zz[d] + 1.0f), 0.f);
                    float numer = fmaxf(diff / (zz[d] - aa[d]), EPSF);
                    float sdiv  = fminf(numer / leaf, CAP);
                    shape += fminf(fabsf(tanf((sdiv - 1.0f) * HPI)), CLIPMAXF);
                    pos += fmaxf(expf(-diff), EPSF);
                }
            }
            double e = exceed, sh = shape, po = pos;
#pragma unroll
            for (int o = 16; o > 0; o >>= 1) {
                e  += __shfl_xor_sync(0xffffffffu, e,  o);
                sh += __shfl_xor_sync(0xffffffffu, sh, o);
                po += __shfl_xor_sync(0xffffffffu, po, o);
            }
            if (lane == 0) {
                atomicAdd(&g_exceed, e);
                atomicAdd(&g_shape, sh);
                atomicAdd(&g_positive, po);
            }
        }
    } else if (b < NS + NG) {
        // ========== Gram: G = O^T O ==========
        float (*sO)[ODim] = (float(*)[ODim])sm;
        int gb = b - NS;
        int g = gb >> 4, kc = gb & 15;
        int P0 = (g == 2) ? 64 : 0;
        int Q0 = (g == 0) ? 0 : 64;

        const float4* og4 = (const float4*)(omega + (size_t)kc * 64 * ODim);
        for (int e = tid; e < 64 * 32; e += 256) ((float4*)sO)[e] = og4[e];
        __syncthreads();

        int pl_ = ((tid >> 4) & 15) * 4, ql_ = (tid & 15) * 4;
        float c[4][4];
#pragma unroll
        for (int m = 0; m < 4; m++)
#pragma unroll
            for (int n = 0; n < 4; n++) c[m][n] = 0.f;
#pragma unroll 8
        for (int k = 0; k < 64; k++) {
            float4 a  = *(const float4*)&sO[k][P0 + pl_];
            float4 bb = *(const float4*)&sO[k][Q0 + ql_];
            c[0][0] += a.x * bb.x; c[0][1] += a.x * bb.y; c[0][2] += a.x * bb.z; c[0][3] += a.x * bb.w;
            c[1][0] += a.y * bb.x; c[1][1] += a.y * bb.y; c[1][2] += a.y * bb.z; c[1][3] += a.y * bb.w;
            c[2][0] += a.z * bb.x; c[2][1] += a.z * bb.y; c[2][2] += a.z * bb.z; c[2][3] += a.z * bb.w;
            c[3][0] += a.w * bb.x; c[3][1] += a.w * bb.y; c[3][2] += a.w * bb.z; c[3][3] += a.w * bb.w;
        }
#pragma unroll
        for (int m = 0; m < 4; m++)
#pragma unroll
            for (int n = 0; n < 4; n++)
                atomicAdd(&g_G[g][(pl_ + m) * 64 + ql_ + n], c[m][n]);

        __threadfence();
        __shared__ bool lastG;
        if (tid == 0) lastG = (atomicAdd(&g_doneG, 1u) == NG - 1);
        __syncthreads();
        if (lastG) {
            __threadfence();
            double acc = 0.0;
            for (int e = tid; e < 3 * 4096; e += 256) {
                int gg = e >> 12, idx = e & 4095;
                float v = __ldcg(&g_G[gg][idx]);
                g_G[gg][idx] = 0.f;
                double d2 = (double)v * (double)v;
                acc += (gg == 1) ? 2.0 * d2 : d2;
            }
#pragma unroll
            for (int o = 16; o > 0; o >>= 1) acc += __shfl_xor_sync(0xffffffffu, acc, o);
            double* sR = (double*)sm;
            __syncthreads();
            if (lane == 0) sR[w] = acc;
            __syncthreads();
            if (tid == 0) {
                double tot = 0.0;
#pragma unroll
                for (int q = 0; q < 8; q++) tot += sR[q];
                g_normG = tot;
            }
        }
    } else {
        // ========== symmetric realdist: triangular tile (bi<=bj) 32 i x 32 j ==========
        float (*sI)[48] = (float(*)[48])sm;            // 6144 B
        int* sIdxI = (int*)(sm + 6144);                // 128 B
        float* sJv = (float*)(sm + 6272);              // 32*17*4 = 2176 B (stride 17: conflict-free)
        int p = b - NS - NG;
        int t = p, bi = 0;
        while (t >= NB2 - bi) { t -= NB2 - bi; bi++; }
        int bj = bi + t;
        int I0 = bi * 32, J0 = bj * 32;

        if (tid < 32) sIdxI[tid] = __ldg(idI + I0 + tid);

        int jglob = J0 + lane;
        int idxj = __ldg(idI + jglob);
        __syncthreads();

        // i-side staging: cl/ch/inv
        for (int e = tid; e < 32 * 16; e += 256) {
            int ii = e >> 4, d = e & 15;
            int ix = sIdxI[ii];
            float cl = __ldg(child + (size_t)ix * 32 + d);
            float ch = __ldg(child + (size_t)ix * 32 + 16 + d);
            sI[ii][d] = cl; sI[ii][16 + d] = ch;
            sI[ii][32 + d] = 1.0f / fmaxf(ch - cl, EPSF);
        }
        // j-side inv staging (computed ONCE per block, not once per warp)
        for (int e = tid; e < 32 * 16; e += 256) {
            int jj = e >> 4, d = e & 15;
            int jx = __ldg(idI + J0 + jj);
            float cl = __ldg(child + (size_t)jx * 32 + d);
            float ch = __ldg(child + (size_t)jx * 32 + 16 + d);
            sJv[jj * 17 + d] = 1.0f / fmaxf(ch - cl, EPSF);
        }
        // gathers: both orders for this warp's 4 i-rows (MLP=8)
        float aij[4], aji[4];
        int ibase = I0 + w * 4;
#pragma unroll
        for (int k = 0; k < 4; k++) {
            int ix = sIdxI[w * 4 + k];
            aij[k] = __ldg(layerDist + (size_t)ix * Cc + idxj);
            aji[k] = __ldg(layerDist + (size_t)idxj * Cc + ix);
        }
        __syncthreads();

        // dim-outer / row-inner: one (l,h,v) j-triple live at a time
        float cd[4] = {0.f,0.f,0.f,0.f};
        float ov[4] = {0.f,0.f,0.f,0.f};
        const float4* pl = (const float4*)(child + (size_t)idxj * 32);
        const float4* ph = (const float4*)(child + (size_t)idxj * 32 + 16);
#pragma unroll
        for (int u = 0; u < 4; u++) {
            float4 l = pl[u], hh = ph[u];
            float4 v2;                              // deduped inverse from smem
            v2.x = sJv[lane * 17 + u * 4 + 0];
            v2.y = sJv[lane * 17 + u * 4 + 1];
            v2.z = sJv[lane * 17 + u * 4 + 2];
            v2.w = sJv[lane * 17 + u * 4 + 3];
#pragma unroll
            for (int k = 0; k < 4; k++) {
                float4 a  = *(const float4*)&sI[w * 4 + k][u * 4];
                float4 bb = *(const float4*)&sI[w * 4 + k][16 + u * 4];
                float4 vi = *(const float4*)&sI[w * 4 + k][32 + u * 4];
                cd[k] += fabsf(a.x - l.x) + fabsf(a.y - l.y)
                       + fabsf(a.z - l.z) + fabsf(a.w - l.w);
                float nx = fmaxf(fminf(bb.x, hh.x) - fmaxf(a.x, l.x), 0.f);
                float ny = fmaxf(fminf(bb.y, hh.y) - fmaxf(a.y, l.y), 0.f);
                float nz = fmaxf(fminf(bb.z, hh.z) - fmaxf(a.z, l.z), 0.f);
                float nw = fmaxf(fminf(bb.w, hh.w) - fmaxf(a.w, l.w), 0.f);
                ov[k] += nx * (vi.x + v2.x) + ny * (vi.y + v2.y)
                       + nz * (vi.z + v2.z) + nw * (vi.w + v2.w);
            }
        }

        float colsumJ = 0.f;
        double ssq = 0.0, ovd = 0.0;
#pragma unroll
        for (int k = 0; k < 4; k++) {
            int ig = ibase + k;
            float r1 = aij[k] + cd[k];
            float r2 = aji[k] + cd[k];
            float wv = 0.f;
            if (ig < jglob) {
                colsumJ += r1;
                ssq += (double)(r1 * r1 + r2 * r2);
                ovd += (double)ov[k];
                wv = r2;
            } else if (ig == jglob) {
                colsumJ += r1;
                ssq += (double)(r1 * r1);
            }
#pragma unroll
            for (int o = 16; o > 0; o >>= 1) wv += __shfl_xor_sync(0xffffffffu, wv, o);
            if (lane == 0 && wv != 0.f) atomicAdd(&g_colR[ig], wv);
        }
        atomicAdd(&g_colR[jglob], colsumJ);

        // block-level fp64 reduce: 1 atomic per scalar per block
#pragma unroll
        for (int o = 16; o > 0; o >>= 1) {
            ssq += __shfl_xor_sync(0xffffffffu, ssq, o);
            ovd += __shfl_xor_sync(0xffffffffu, ovd, o);
        }
        if (lane == 0) { sAcc[w][0] = ssq; sAcc[w][1] = ovd; }
        __syncthreads();
        if (tid == 0) {
            double t0 = 0.0, t1 = 0.0;
#pragma unroll
            for (int q = 0; q < 8; q++) { t0 += sAcc[q][0]; t1 += sAcc[q][1]; }
            atomicAdd(&g_sumsqR, t0);
            atomicAdd(&g_overlap, t1);
        }
    }

    // ================= last-block finalize + state restore =================
    __threadfence();
    if (tid == 0) isLast = (atomicAdd(&g_done, 1u) == NTOT - 1);
    __syncthreads();
    if (!isLast) return;
    __threadfence();

    double S1 = 0, S2 = 0, T1 = 0, CR = 0, CRI = 0, CRT = 0, s2a = 0;
#pragma unroll
    for (int q = 0; q < 4; q++) {
        int j = tid + q * 256;
        double inn = (double)__ldcg(&g_inner[j]);
        double tj  = (double)__ldcg(&g_t[j]);
        double cr  = (double)__ldcg(&g_colR[j]);
        g_colR[j] = 0.f;
        S1 += inn; S2 += inn * inn; T1 += inn * tj;
        CR += cr; CRI += cr * inn; CRT += cr * tj; s2a += cr * cr;
    }
#pragma unroll
    for (int o = 16; o > 0; o >>= 1) {
        S1 += __shfl_xor_sync(0xffffffffu, S1, o);
        S2 += __shfl_xor_sync(0xffffffffu, S2, o);
        T1 += __shfl_xor_sync(0xffffffffu, T1, o);
        CR += __shfl_xor_sync(0xffffffffu, CR, o);
        CRI += __shfl_xor_sync(0xffffffffu, CRI, o);
        CRT += __shfl_xor_sync(0xffffffffu, CRT, o);
        s2a += __shfl_xor_sync(0xffffffffu, s2a, o);
    }
    double* sR = (double*)sm;
    __syncthreads();
    if (lane == 0) {
        sR[w * 7 + 0] = S1; sR[w * 7 + 1] = S2; sR[w * 7 + 2] = T1;
        sR[w * 7 + 3] = CR; sR[w * 7 + 4] = CRI; sR[w * 7 + 5] = CRT;
        sR[w * 7 + 6] = s2a;
    }
    __syncthreads();
    if (tid == 0) {
        double a0 = 0, a1 = 0, a2 = 0, a3 = 0, a4 = 0, a5 = 0, a6 = 0;
#pragma unroll
        for (int q = 0; q < 8; q++) {
            a0 += sR[q * 7 + 0]; a1 += sR[q * 7 + 1]; a2 += sR[q * 7 + 2];
            a3 += sR[q * 7 + 3]; a4 += sR[q * 7 + 4]; a5 += sR[q * 7 + 5];
            a6 += sR[q * 7 + 6];
        }
        double sumsqA = 2.0 * Nn * a1 + 2.0 * a0 * a0 - 8.0 * a2 + 4.0 * __ldcg(&g_normG);
        double s1 = a0 * a3 + (double)Nn * a4 - 2.0 * a5 + (double)EPSF * a3;
        double sumsqR = __ldcg(&g_sumsqR);
        double nR = fmax(sqrt(sumsqR), 1e-15);
        double nA = fmax(sqrt(fmax(sumsqA, 0.0)), 1e-15);
        double val = sumsqA / (nA * nA) - 2.0 * (s1 / nR) / nA + (double)Nn * (a6 / (nR * nR));
        double lossDist = sqrt(fmax(val, 0.0));
        out[0] = (float)(lossDist + __ldcg(&g_shape) + __ldcg(&g_exceed)
                         + __ldcg(&g_overlap) + __ldcg(&g_positive));
        g_sumsqR = 0.0; g_overlap = 0.0; g_exceed = 0.0; g_shape = 0.0; g_positive = 0.0;
        g_done = 0u; g_doneS = 0u; g_doneG = 0u;
    }
}

// ---------------- launch ----------------
extern "C" void kernel_launch(void* const* d_in, const int* in_sizes, int n_in,
                              void* d_out, int out_size) {
    const int*   idI    = (const int*)d_in[0];
    const int*   par    = (const int*)d_in[1];
    const float* omega  = (const float*)d_in[2];
    const float* child  = (const float*)d_in[3];
    const float* resv   = (const float*)d_in[4];
    const float* leaves = (const float*)d_in[5];
    const float* layerD = (const float*)d_in[6];
    (void)in_sizes; (void)n_in; (void)out_size;

    k_all<<<NTOT, 256>>>(idI, par, omega, child, resv, leaves, layerD, (float*)d_out);
}